// round 6
// baseline (speedup 1.0000x reference)
#include <cuda_runtime.h>
#include <cuda_bf16.h>
#include <cstdint>

// ---------------------------------------------------------------------------
// cls_model: FPS (cycle-collapsed) -> [KNN(32)+conv1..4 fused] -> conv5+pool
//            -> fused FC head.   B=4, N=16384, C=3, N_C=1024, K=32
// R5: KNN top-32 via warp-local extraction + smem rank (no block-sync rounds);
//     FC head fused into one kernel; fps warp-shuffle final reduce.
// ---------------------------------------------------------------------------

#define NB 4
#define NPTS 16384
#define NC 1024
#define KNN 32

#define FUSED_GRID_X 128
#define CONV5_GRID_X 64
#define WARM_BLOCKS 64

// ---- device scratch (no allocations allowed) ----
__device__ int   g_cnt[NB];
__device__ float g_cent[NB * NC * 3];
__device__ float g_h4[(size_t)NB * NC * KNN * 128];
__device__ int   g_pool[NB * 1024];     // maxpool accumulator (float bits, >=0)
__device__ float g_sink[WARM_BLOCKS];   // keeps warm-up loads alive

static __device__ __forceinline__ float f_inf() { return __int_as_float(0x7f800000); }
// monotone order-preserving float->uint map (d >= -0 here; fully general anyway)
static __device__ __forceinline__ unsigned f_ord(float f) {
    unsigned b = __float_as_uint(f);
    return b ^ ((unsigned)(((int)b) >> 31) | 0x80000000u);
}

// ===========================================================================
// K1: FPS with cycle detection (blocks 0..NB-1) + L2 warm-up for FC/conv5
// weights (blocks NB.., concurrent on idle SMs).
// FPS arithmetic bit-exact vs reference; argmax tie -> lowest index.
// ===========================================================================
__global__ __launch_bounds__(512) void k_fps(const float* __restrict__ x,
                                             const int* __restrict__ far0,
                                             const float* __restrict__ fw1,
                                             const float* __restrict__ fw2,
                                             const float* __restrict__ w5) {
    const int t = threadIdx.x;

    if (blockIdx.x >= NB) {
        const int wb = blockIdx.x - NB;
        float s = 0.0f;
        const float4* p1 = (const float4*)fw1;
        for (int i = wb * 512 + t; i < 512 * 256; i += WARM_BLOCKS * 512) {
            float4 v = __ldg(p1 + i); s += v.x + v.y + v.z + v.w;
        }
        const float4* p2 = (const float4*)fw2;
        for (int i = wb * 512 + t; i < 256 * 128; i += WARM_BLOCKS * 512) {
            float4 v = __ldg(p2 + i); s += v.x + v.y + v.z + v.w;
        }
        const float4* p5 = (const float4*)w5;
        for (int i = wb * 512 + t; i < 1024 * 32; i += WARM_BLOCKS * 512) {
            float4 v = __ldg(p5 + i); s += v.x + v.y + v.z + v.w;
        }
        if (s == -1.2345678e38f && t == 0) g_sink[wb] = s;  // defeats DCE
        return;
    }

    const int b = blockIdx.x;
    const float* xb = x + (size_t)b * NPTS * 3;

    float px[32], py[32], pz[32];
#pragma unroll
    for (int i = 0; i < 32; i++) {
        int n = i * 512 + t;
        px[i] = xb[n * 3 + 0];
        py[i] = xb[n * 3 + 1];
        pz[i] = xb[n * 3 + 2];
    }

    __shared__ unsigned seen[512];
    __shared__ float cc[3];
    __shared__ float rd[16]; __shared__ int rn[16];
    __shared__ float rx[16], ry[16], rz[16];
    __shared__ int sdone;

    g_pool[b * 1024 + t] = 0;
    g_pool[b * 1024 + 512 + t] = 0;
    seen[t] = 0u;
    __syncthreads();

    if (t == 0) {
        int f = far0[b];
        seen[f >> 5] = 1u << (f & 31);
        float cx = xb[f * 3 + 0], cy = xb[f * 3 + 1], cz = xb[f * 3 + 2];
        cc[0] = cx; cc[1] = cy; cc[2] = cz;
        g_cent[(b * NC + 0) * 3 + 0] = cx;
        g_cent[(b * NC + 0) * 3 + 1] = cy;
        g_cent[(b * NC + 0) * 3 + 2] = cz;
        sdone = 0;
    }
    __syncthreads();

    int cnt = 1;
    for (int it = 1; it < NC; it++) {
        float cx = cc[0], cy = cc[1], cz = cc[2];
        float best = -1.0f; int bn = 0;
        float bx = 0.f, by = 0.f, bz = 0.f;
#pragma unroll
        for (int i = 0; i < 32; i++) {
            float dx = __fsub_rn(px[i], cx);
            float dy = __fsub_rn(py[i], cy);
            float dz = __fsub_rn(pz[i], cz);
            float d = __fadd_rn(__fadd_rn(__fmul_rn(dx, dx), __fmul_rn(dy, dy)),
                                __fmul_rn(dz, dz));
            int n = i * 512 + t;
            if (d > best) { best = d; bn = n; bx = px[i]; by = py[i]; bz = pz[i]; }
        }
#pragma unroll
        for (int o = 16; o > 0; o >>= 1) {
            float od = __shfl_down_sync(0xffffffffu, best, o);
            int   on = __shfl_down_sync(0xffffffffu, bn,   o);
            float ox = __shfl_down_sync(0xffffffffu, bx,   o);
            float oy = __shfl_down_sync(0xffffffffu, by,   o);
            float oz = __shfl_down_sync(0xffffffffu, bz,   o);
            if (od > best || (od == best && on < bn)) {
                best = od; bn = on; bx = ox; by = oy; bz = oz;
            }
        }
        int w = t >> 5;
        if ((t & 31) == 0) { rd[w] = best; rn[w] = bn; rx[w] = bx; ry[w] = by; rz[w] = bz; }
        __syncthreads();
        if (t < 32) {
            // warp0 reduces the 16 partials by shuffle (lanes >=16 hold neutral)
            float pd = (t < 16) ? rd[t] : -1.0f;
            int   pn = (t < 16) ? rn[t] : (1 << 30);
            float pxx = (t < 16) ? rx[t] : 0.f;
            float pyy = (t < 16) ? ry[t] : 0.f;
            float pzz = (t < 16) ? rz[t] : 0.f;
#pragma unroll
            for (int o = 8; o > 0; o >>= 1) {
                float od = __shfl_down_sync(0xffffffffu, pd, o);
                int   on = __shfl_down_sync(0xffffffffu, pn, o);
                float ox = __shfl_down_sync(0xffffffffu, pxx, o);
                float oy = __shfl_down_sync(0xffffffffu, pyy, o);
                float oz = __shfl_down_sync(0xffffffffu, pzz, o);
                if (od > pd || (od == pd && on < pn)) {
                    pd = od; pn = on; pxx = ox; pyy = oy; pzz = oz;
                }
            }
            if (t == 0) {
                unsigned bit = 1u << (pn & 31);
                if (seen[pn >> 5] & bit) {
                    sdone = 1;
                } else {
                    seen[pn >> 5] |= bit;
                    g_cent[(b * NC + cnt) * 3 + 0] = pxx;
                    g_cent[(b * NC + cnt) * 3 + 1] = pyy;
                    g_cent[(b * NC + cnt) * 3 + 2] = pzz;
                    cc[0] = pxx; cc[1] = pyy; cc[2] = pzz;
                }
            }
        }
        __syncthreads();
        if (sdone) break;
        cnt++;
    }
    if (t == 0) g_cnt[b] = cnt;
}

// ===========================================================================
// K2: fused KNN(32) + conv1..conv4 per distinct centroid. 512 threads.
// KNN top-32: each warp extracts its local top-32 (shuffle-only rounds with
// owner-lane rescan), then 512 candidates ranked in smem. Selected SET is
// bit-identical to reference top_k ((d2, idx) lex); wlist order is irrelevant
// because the downstream maxpool is position-order-invariant.
// ===========================================================================
__global__ __launch_bounds__(512) void k_fused(
    const float* __restrict__ x,
    const float* __restrict__ w1, const float* __restrict__ b1,
    const float* __restrict__ w2, const float* __restrict__ b2,
    const float* __restrict__ w3, const float* __restrict__ b3,
    const float* __restrict__ w4, const float* __restrict__ b4) {
    const int b = blockIdx.y;
    const int cnt = g_cnt[b];
    const int t = threadIdx.x;
    const int lane = t & 31, w = t >> 5;
    const float* xb = x + (size_t)b * NPTS * 3;

    __shared__ unsigned long long cand[512];
    __shared__ int wlist[KNN];
    __shared__ float P[KNN][4];
    __shared__ float Ha[KNN][65];
    __shared__ float Hb[KNN][65];

    for (int ci = blockIdx.x; ci < cnt; ci += FUSED_GRID_X) {
        // ---------------- distances (bit-exact vs reference) ----------------
        const float cx = g_cent[(b * NC + ci) * 3 + 0];
        const float cy = g_cent[(b * NC + ci) * 3 + 1];
        const float cz = g_cent[(b * NC + ci) * 3 + 2];
        const float c2 = __fadd_rn(__fadd_rn(__fmul_rn(cx, cx), __fmul_rn(cy, cy)),
                                   __fmul_rn(cz, cz));

        float d[32];
#pragma unroll
        for (int i = 0; i < 32; i++) {
            int n = i * 512 + t;
            float X = xb[n * 3 + 0], Y = xb[n * 3 + 1], Z = xb[n * 3 + 2];
            float x2 = __fadd_rn(__fadd_rn(__fmul_rn(X, X), __fmul_rn(Y, Y)),
                                 __fmul_rn(Z, Z));
            float dt = __fadd_rn(__fadd_rn(__fmul_rn(cx, X), __fmul_rn(cy, Y)),
                                 __fmul_rn(cz, Z));
            d[i] = __fsub_rn(__fadd_rn(c2, x2), __fmul_rn(2.0f, dt));
        }

        // ------------- phase 1: warp-local top-32 extraction -------------
        // thread-local running min (u, n)
        unsigned lu = 0xFFFFFFFFu; int ln = 1 << 30;
#pragma unroll
        for (int i = 0; i < 32; i++) {
            unsigned u = f_ord(d[i]);
            int n = (i << 9) + t;
            if (u < lu || (u == lu && n < ln)) { lu = u; ln = n; }
        }
        for (int r = 0; r < KNN; r++) {
            unsigned ru = lu; int rn2 = ln;
#pragma unroll
            for (int o = 16; o > 0; o >>= 1) {
                unsigned ou = __shfl_down_sync(0xffffffffu, ru, o);
                int      on = __shfl_down_sync(0xffffffffu, rn2, o);
                if (ou < ru || (ou == ru && on < rn2)) { ru = ou; rn2 = on; }
            }
            ru = __shfl_sync(0xffffffffu, ru, 0);
            rn2 = __shfl_sync(0xffffffffu, rn2, 0);
            if (lane == 0)
                cand[w * 32 + r] = ((unsigned long long)ru << 14) | (unsigned)rn2;
            if (ln == rn2) {
                // this thread owned the winner: clear slot, rescan
#pragma unroll
                for (int i = 0; i < 32; i++)
                    if ((i << 9) + t == rn2) d[i] = f_inf();
                lu = 0xFFFFFFFFu; ln = 1 << 30;
#pragma unroll
                for (int i = 0; i < 32; i++) {
                    unsigned u = f_ord(d[i]);
                    int n = (i << 9) + t;
                    if (u < lu || (u == lu && n < ln)) { lu = u; ln = n; }
                }
            }
        }
        __syncthreads();

        // ------------- phase 2: rank 512 candidates, keep 32 smallest ------
        {
            unsigned long long k0 = cand[t];
            int r = 0;
#pragma unroll 8
            for (int j = 0; j < 512; j++) r += (cand[j] < k0);
            if (r < KNN) wlist[r] = (int)(k0 & 0x3FFFull);
        }
        __syncthreads();

        // gather neighbor coords
        if (t < KNN) {
            int n = wlist[t];
            P[t][0] = xb[n * 3 + 0];
            P[t][1] = xb[n * 3 + 1];
            P[t][2] = xb[n * 3 + 2];
        }
        __syncthreads();

        // conv1: 3 -> 64
        {
            int ch = t & 63, p0 = t >> 6;
            float wa = __ldg(w1 + ch * 3 + 0), wb = __ldg(w1 + ch * 3 + 1),
                  wc = __ldg(w1 + ch * 3 + 2), bb = __ldg(b1 + ch);
#pragma unroll
            for (int k = 0; k < 4; k++) {
                int p = p0 + 8 * k;
                float v = fmaf(wa, P[p][0], fmaf(wb, P[p][1], fmaf(wc, P[p][2], bb)));
                Ha[p][ch] = fmaxf(v, 0.0f);
            }
        }
        __syncthreads();

        // conv2: 64 -> 64 (Ha -> Hb)
        {
            int ch = t & 63, p0 = t >> 6;
            float bb = __ldg(b2 + ch);
            float a0 = bb, a1 = bb, a2 = bb, a3 = bb;
            const float* wr = w2 + ch * 64;
#pragma unroll 8
            for (int j = 0; j < 64; j++) {
                float ww = __ldg(wr + j);
                a0 = fmaf(ww, Ha[p0 +  0][j], a0);
                a1 = fmaf(ww, Ha[p0 +  8][j], a1);
                a2 = fmaf(ww, Ha[p0 + 16][j], a2);
                a3 = fmaf(ww, Ha[p0 + 24][j], a3);
            }
            Hb[p0 +  0][ch] = fmaxf(a0, 0.0f);
            Hb[p0 +  8][ch] = fmaxf(a1, 0.0f);
            Hb[p0 + 16][ch] = fmaxf(a2, 0.0f);
            Hb[p0 + 24][ch] = fmaxf(a3, 0.0f);
        }
        __syncthreads();

        // conv3: 64 -> 64 (Hb -> Ha)
        {
            int ch = t & 63, p0 = t >> 6;
            float bb = __ldg(b3 + ch);
            float a0 = bb, a1 = bb, a2 = bb, a3 = bb;
            const float* wr = w3 + ch * 64;
#pragma unroll 8
            for (int j = 0; j < 64; j++) {
                float ww = __ldg(wr + j);
                a0 = fmaf(ww, Hb[p0 +  0][j], a0);
                a1 = fmaf(ww, Hb[p0 +  8][j], a1);
                a2 = fmaf(ww, Hb[p0 + 16][j], a2);
                a3 = fmaf(ww, Hb[p0 + 24][j], a3);
            }
            Ha[p0 +  0][ch] = fmaxf(a0, 0.0f);
            Ha[p0 +  8][ch] = fmaxf(a1, 0.0f);
            Ha[p0 + 16][ch] = fmaxf(a2, 0.0f);
            Ha[p0 + 24][ch] = fmaxf(a3, 0.0f);
        }
        __syncthreads();

        // conv4: 64 -> 128 (Ha -> g_h4, coalesced)
        {
            int oc = t & 127, p0 = t >> 7;
            float bb = __ldg(b4 + oc);
            float acc[8];
#pragma unroll
            for (int k = 0; k < 8; k++) acc[k] = bb;
            const float* wr = w4 + oc * 64;
#pragma unroll 4
            for (int j = 0; j < 64; j++) {
                float ww = __ldg(wr + j);
#pragma unroll
                for (int k = 0; k < 8; k++)
                    acc[k] = fmaf(ww, Ha[p0 + 4 * k][j], acc[k]);
            }
            float* out = g_h4 + (size_t)(b * NC + ci) * KNN * 128;
#pragma unroll
            for (int k = 0; k < 8; k++)
                out[(p0 + 4 * k) * 128 + oc] = fmaxf(acc[k], 0.0f);
        }
        __syncthreads();
    }
}

// ===========================================================================
// K3: conv5 (128->1024) + relu + local position-max, atomicMax into g_pool.
// ===========================================================================
__global__ __launch_bounds__(128) void k_conv5(const float* __restrict__ w5,
                                               const float* __restrict__ b5) {
    const int b = blockIdx.y;
    const int cnt = g_cnt[b];
    const int nwork = cnt * 8;
    const int t = threadIdx.x;

    __shared__ float H[32 * 128];

    for (int wkr = blockIdx.x; wkr < nwork; wkr += CONV5_GRID_X) {
        const int ci = wkr >> 3, z = wkr & 7;
        const float* h4 = g_h4 + (size_t)(b * NC + ci) * KNN * 128;
        for (int i = t; i < 32 * 128; i += 128) H[i] = h4[i];
        __syncthreads();

        const int oc = z * 128 + t;
        float acc[32];
#pragma unroll
        for (int p = 0; p < 32; p++) acc[p] = 0.0f;
        const float* wr = w5 + (size_t)oc * 128;
#pragma unroll 4
        for (int j = 0; j < 128; j++) {
            float ww = __ldg(wr + j);
#pragma unroll
            for (int p = 0; p < 32; p++) acc[p] = fmaf(ww, H[p * 128 + j], acc[p]);
        }
        float m = acc[0];
#pragma unroll
        for (int p = 1; p < 32; p++) m = fmaxf(m, acc[p]);
        m = fmaxf(m + __ldg(b5 + oc), 0.0f);
        atomicMax(&g_pool[b * 1024 + oc], __float_as_int(m));
        __syncthreads();
    }
}

// ===========================================================================
// K4: fused FC head. One block (512 thr) per batch; L2-warm weights after
// first replay + warm-up, so float4 streaming is fast.
// ===========================================================================
__global__ __launch_bounds__(512) void k_fc(
    const float* __restrict__ fw1, const float* __restrict__ fb1,
    const float* __restrict__ fw2, const float* __restrict__ fb2,
    const float* __restrict__ fw3, const float* __restrict__ fb3,
    float* __restrict__ out) {
    const int b = blockIdx.x;
    const int t = threadIdx.x;
    __shared__ float G[1024];
    __shared__ float A1[512];
    __shared__ float A2[256];

    G[t]       = __int_as_float(g_pool[b * 1024 + t]);
    G[t + 512] = __int_as_float(g_pool[b * 1024 + 512 + t]);
    __syncthreads();

    {
        const float4* wr = (const float4*)(fw1 + (size_t)t * 1024);
        float a0 = 0.f, a1 = 0.f, a2 = 0.f, a3 = 0.f;
#pragma unroll 8
        for (int i = 0; i < 256; i++) {
            float4 ww = __ldg(wr + i);
            a0 = fmaf(ww.x, G[4 * i + 0], a0);
            a1 = fmaf(ww.y, G[4 * i + 1], a1);
            a2 = fmaf(ww.z, G[4 * i + 2], a2);
            a3 = fmaf(ww.w, G[4 * i + 3], a3);
        }
        A1[t] = fmaxf(((a0 + a1) + (a2 + a3)) + __ldg(fb1 + t), 0.0f);
    }
    __syncthreads();
    if (t < 256) {
        const float4* wr = (const float4*)(fw2 + (size_t)t * 512);
        float a0 = 0.f, a1 = 0.f, a2 = 0.f, a3 = 0.f;
#pragma unroll 8
        for (int i = 0; i < 128; i++) {
            float4 ww = __ldg(wr + i);
            a0 = fmaf(ww.x, A1[4 * i + 0], a0);
            a1 = fmaf(ww.y, A1[4 * i + 1], a1);
            a2 = fmaf(ww.z, A1[4 * i + 2], a2);
            a3 = fmaf(ww.w, A1[4 * i + 3], a3);
        }
        A2[t] = fmaxf(((a0 + a1) + (a2 + a3)) + __ldg(fb2 + t), 0.0f);
    }
    __syncthreads();
    if (t < 96) {
        const int o = t >> 5, lane = t & 31;
        const float4* wr = (const float4*)(fw3 + (size_t)o * 256);
        float4 wA = __ldg(wr + lane);
        float4 wB = __ldg(wr + 32 + lane);
        float s = fmaf(wA.x, A2[4 * lane + 0], fmaf(wA.y, A2[4 * lane + 1],
                  fmaf(wA.z, A2[4 * lane + 2], wA.w * A2[4 * lane + 3])));
        s = fmaf(wB.x, A2[128 + 4 * lane + 0], fmaf(wB.y, A2[128 + 4 * lane + 1],
            fmaf(wB.z, A2[128 + 4 * lane + 2], fmaf(wB.w, A2[128 + 4 * lane + 3], s))));
#pragma unroll
        for (int off = 16; off > 0; off >>= 1)
            s += __shfl_down_sync(0xffffffffu, s, off);
        if (lane == 0) out[b * 3 + o] = s + __ldg(fb3 + o);
    }
}

// ===========================================================================
extern "C" void kernel_launch(void* const* d_in, const int* in_sizes, int n_in,
                              void* d_out, int out_size) {
    const float* x    = (const float*)d_in[0];
    const int*   far0 = (const int*)d_in[1];
    const float* w1 = (const float*)d_in[2];  const float* b1 = (const float*)d_in[3];
    const float* w2 = (const float*)d_in[4];  const float* b2 = (const float*)d_in[5];
    const float* w3 = (const float*)d_in[6];  const float* b3 = (const float*)d_in[7];
    const float* w4 = (const float*)d_in[8];  const float* b4 = (const float*)d_in[9];
    const float* w5 = (const float*)d_in[10]; const float* b5 = (const float*)d_in[11];
    const float* fw1 = (const float*)d_in[12]; const float* fb1 = (const float*)d_in[13];
    const float* fw2 = (const float*)d_in[14]; const float* fb2 = (const float*)d_in[15];
    const float* fw3 = (const float*)d_in[16]; const float* fb3 = (const float*)d_in[17];
    float* out = (float*)d_out;

    k_fps<<<NB + WARM_BLOCKS, 512>>>(x, far0, fw1, fw2, w5);
    k_fused<<<dim3(FUSED_GRID_X, NB), 512>>>(x, w1, b1, w2, b2, w3, b3, w4, b4);
    k_conv5<<<dim3(CONV5_GRID_X, NB), 128>>>(w5, b5);
    k_fc<<<NB, 512>>>(fw1, fb1, fw2, fb2, fw3, fb3, out);
}

// round 7
// speedup vs baseline: 1.0105x; 1.0105x over previous
#include <cuda_runtime.h>
#include <cuda_bf16.h>
#include <cstdint>

// ---------------------------------------------------------------------------
// cls_model: FPS (cycle-collapsed) -> [KNN(32)+conv1..4 fused] -> conv5+pool
//            -> parallel FC head.   B=4, N=16384, C=3, N_C=1024, K=32
// R6: R5's warp-local KNN + R4's proven parallel FC split + re-tiled conv5
//     (8x less serial FMA depth per thread).
// ---------------------------------------------------------------------------

#define NB 4
#define NPTS 16384
#define NC 1024
#define KNN 32

#define FUSED_GRID_X 128
#define CONV5_GRID_X 16      // x-dim: ci stride; z-dim: 16 oc-tiles of 64
#define WARM_BLOCKS 64

// ---- device scratch (no allocations allowed) ----
__device__ int   g_cnt[NB];
__device__ float g_cent[NB * NC * 3];
__device__ float g_h4[(size_t)NB * NC * KNN * 128];
__device__ int   g_pool[NB * 1024];     // maxpool accumulator (float bits, >=0)
__device__ float g_a1[NB * 512];
__device__ float g_a2[NB * 256];
__device__ float g_sink[WARM_BLOCKS];

static __device__ __forceinline__ float f_inf() { return __int_as_float(0x7f800000); }
static __device__ __forceinline__ unsigned f_ord(float f) {
    unsigned b = __float_as_uint(f);
    return b ^ ((unsigned)(((int)b) >> 31) | 0x80000000u);
}

// ===========================================================================
// K1: FPS with cycle detection (blocks 0..NB-1) + L2 warm-up (blocks NB..).
// FPS arithmetic bit-exact vs reference; argmax tie -> lowest index.
// ===========================================================================
__global__ __launch_bounds__(512) void k_fps(const float* __restrict__ x,
                                             const int* __restrict__ far0,
                                             const float* __restrict__ fw1,
                                             const float* __restrict__ fw2,
                                             const float* __restrict__ w5) {
    const int t = threadIdx.x;

    if (blockIdx.x >= NB) {
        const int wb = blockIdx.x - NB;
        float s = 0.0f;
        const float4* p1 = (const float4*)fw1;
        for (int i = wb * 512 + t; i < 512 * 256; i += WARM_BLOCKS * 512) {
            float4 v = __ldg(p1 + i); s += v.x + v.y + v.z + v.w;
        }
        const float4* p2 = (const float4*)fw2;
        for (int i = wb * 512 + t; i < 256 * 128; i += WARM_BLOCKS * 512) {
            float4 v = __ldg(p2 + i); s += v.x + v.y + v.z + v.w;
        }
        const float4* p5 = (const float4*)w5;
        for (int i = wb * 512 + t; i < 1024 * 32; i += WARM_BLOCKS * 512) {
            float4 v = __ldg(p5 + i); s += v.x + v.y + v.z + v.w;
        }
        if (s == -1.2345678e38f && t == 0) g_sink[wb] = s;  // defeats DCE
        return;
    }

    const int b = blockIdx.x;
    const float* xb = x + (size_t)b * NPTS * 3;

    float px[32], py[32], pz[32];
#pragma unroll
    for (int i = 0; i < 32; i++) {
        int n = i * 512 + t;
        px[i] = xb[n * 3 + 0];
        py[i] = xb[n * 3 + 1];
        pz[i] = xb[n * 3 + 2];
    }

    __shared__ unsigned seen[512];
    __shared__ float cc[3];
    __shared__ float rd[16]; __shared__ int rn[16];
    __shared__ float rx[16], ry[16], rz[16];
    __shared__ int sdone;

    g_pool[b * 1024 + t] = 0;
    g_pool[b * 1024 + 512 + t] = 0;
    seen[t] = 0u;
    __syncthreads();

    if (t == 0) {
        int f = far0[b];
        seen[f >> 5] = 1u << (f & 31);
        float cx = xb[f * 3 + 0], cy = xb[f * 3 + 1], cz = xb[f * 3 + 2];
        cc[0] = cx; cc[1] = cy; cc[2] = cz;
        g_cent[(b * NC + 0) * 3 + 0] = cx;
        g_cent[(b * NC + 0) * 3 + 1] = cy;
        g_cent[(b * NC + 0) * 3 + 2] = cz;
        sdone = 0;
    }
    __syncthreads();

    int cnt = 1;
    for (int it = 1; it < NC; it++) {
        float cx = cc[0], cy = cc[1], cz = cc[2];
        float best = -1.0f; int bn = 0;
        float bx = 0.f, by = 0.f, bz = 0.f;
#pragma unroll
        for (int i = 0; i < 32; i++) {
            float dx = __fsub_rn(px[i], cx);
            float dy = __fsub_rn(py[i], cy);
            float dz = __fsub_rn(pz[i], cz);
            float d = __fadd_rn(__fadd_rn(__fmul_rn(dx, dx), __fmul_rn(dy, dy)),
                                __fmul_rn(dz, dz));
            int n = i * 512 + t;
            if (d > best) { best = d; bn = n; bx = px[i]; by = py[i]; bz = pz[i]; }
        }
#pragma unroll
        for (int o = 16; o > 0; o >>= 1) {
            float od = __shfl_down_sync(0xffffffffu, best, o);
            int   on = __shfl_down_sync(0xffffffffu, bn,   o);
            float ox = __shfl_down_sync(0xffffffffu, bx,   o);
            float oy = __shfl_down_sync(0xffffffffu, by,   o);
            float oz = __shfl_down_sync(0xffffffffu, bz,   o);
            if (od > best || (od == best && on < bn)) {
                best = od; bn = on; bx = ox; by = oy; bz = oz;
            }
        }
        int w = t >> 5;
        if ((t & 31) == 0) { rd[w] = best; rn[w] = bn; rx[w] = bx; ry[w] = by; rz[w] = bz; }
        __syncthreads();
        if (t < 32) {
            float pd = (t < 16) ? rd[t] : -1.0f;
            int   pn = (t < 16) ? rn[t] : (1 << 30);
            float pxx = (t < 16) ? rx[t] : 0.f;
            float pyy = (t < 16) ? ry[t] : 0.f;
            float pzz = (t < 16) ? rz[t] : 0.f;
#pragma unroll
            for (int o = 8; o > 0; o >>= 1) {
                float od = __shfl_down_sync(0xffffffffu, pd, o);
                int   on = __shfl_down_sync(0xffffffffu, pn, o);
                float ox = __shfl_down_sync(0xffffffffu, pxx, o);
                float oy = __shfl_down_sync(0xffffffffu, pyy, o);
                float oz = __shfl_down_sync(0xffffffffu, pzz, o);
                if (od > pd || (od == pd && on < pn)) {
                    pd = od; pn = on; pxx = ox; pyy = oy; pzz = oz;
                }
            }
            if (t == 0) {
                unsigned bit = 1u << (pn & 31);
                if (seen[pn >> 5] & bit) {
                    sdone = 1;
                } else {
                    seen[pn >> 5] |= bit;
                    g_cent[(b * NC + cnt) * 3 + 0] = pxx;
                    g_cent[(b * NC + cnt) * 3 + 1] = pyy;
                    g_cent[(b * NC + cnt) * 3 + 2] = pzz;
                    cc[0] = pxx; cc[1] = pyy; cc[2] = pzz;
                }
            }
        }
        __syncthreads();
        if (sdone) break;
        cnt++;
    }
    if (t == 0) g_cnt[b] = cnt;
}

// ===========================================================================
// K2: fused KNN(32) + conv1..conv4 per distinct centroid. 512 threads.
// KNN top-32: warp-local extraction (shuffle-only) + smem rank of 512
// candidates. Selected SET bit-identical to reference top_k ((d2, idx) lex);
// wlist order irrelevant (maxpool is position-order-invariant).
// ===========================================================================
__global__ __launch_bounds__(512) void k_fused(
    const float* __restrict__ x,
    const float* __restrict__ w1, const float* __restrict__ b1,
    const float* __restrict__ w2, const float* __restrict__ b2,
    const float* __restrict__ w3, const float* __restrict__ b3,
    const float* __restrict__ w4, const float* __restrict__ b4) {
    const int b = blockIdx.y;
    const int cnt = g_cnt[b];
    const int t = threadIdx.x;
    const int lane = t & 31, w = t >> 5;
    const float* xb = x + (size_t)b * NPTS * 3;

    __shared__ unsigned long long cand[512];
    __shared__ int wlist[KNN];
    __shared__ float P[KNN][4];
    __shared__ float Ha[KNN][65];
    __shared__ float Hb[KNN][65];

    for (int ci = blockIdx.x; ci < cnt; ci += FUSED_GRID_X) {
        const float cx = g_cent[(b * NC + ci) * 3 + 0];
        const float cy = g_cent[(b * NC + ci) * 3 + 1];
        const float cz = g_cent[(b * NC + ci) * 3 + 2];
        const float c2 = __fadd_rn(__fadd_rn(__fmul_rn(cx, cx), __fmul_rn(cy, cy)),
                                   __fmul_rn(cz, cz));

        float d[32];
#pragma unroll
        for (int i = 0; i < 32; i++) {
            int n = i * 512 + t;
            float X = xb[n * 3 + 0], Y = xb[n * 3 + 1], Z = xb[n * 3 + 2];
            float x2 = __fadd_rn(__fadd_rn(__fmul_rn(X, X), __fmul_rn(Y, Y)),
                                 __fmul_rn(Z, Z));
            float dt = __fadd_rn(__fadd_rn(__fmul_rn(cx, X), __fmul_rn(cy, Y)),
                                 __fmul_rn(cz, Z));
            d[i] = __fsub_rn(__fadd_rn(c2, x2), __fmul_rn(2.0f, dt));
        }

        // phase 1: warp-local top-32 extraction
        unsigned lu = 0xFFFFFFFFu; int ln = 1 << 30;
#pragma unroll
        for (int i = 0; i < 32; i++) {
            unsigned u = f_ord(d[i]);
            int n = (i << 9) + t;
            if (u < lu || (u == lu && n < ln)) { lu = u; ln = n; }
        }
        for (int r = 0; r < KNN; r++) {
            unsigned ru = lu; int rn2 = ln;
#pragma unroll
            for (int o = 16; o > 0; o >>= 1) {
                unsigned ou = __shfl_down_sync(0xffffffffu, ru, o);
                int      on = __shfl_down_sync(0xffffffffu, rn2, o);
                if (ou < ru || (ou == ru && on < rn2)) { ru = ou; rn2 = on; }
            }
            ru = __shfl_sync(0xffffffffu, ru, 0);
            rn2 = __shfl_sync(0xffffffffu, rn2, 0);
            if (lane == 0)
                cand[w * 32 + r] = ((unsigned long long)ru << 14) | (unsigned)rn2;
            if (ln == rn2) {
#pragma unroll
                for (int i = 0; i < 32; i++)
                    if ((i << 9) + t == rn2) d[i] = f_inf();
                lu = 0xFFFFFFFFu; ln = 1 << 30;
#pragma unroll
                for (int i = 0; i < 32; i++) {
                    unsigned u = f_ord(d[i]);
                    int n = (i << 9) + t;
                    if (u < lu || (u == lu && n < ln)) { lu = u; ln = n; }
                }
            }
        }
        __syncthreads();

        // phase 2: rank 512 candidates, keep 32 smallest
        {
            unsigned long long k0 = cand[t];
            int r = 0;
#pragma unroll 8
            for (int j = 0; j < 512; j++) r += (cand[j] < k0);
            if (r < KNN) wlist[r] = (int)(k0 & 0x3FFFull);
        }
        __syncthreads();

        if (t < KNN) {
            int n = wlist[t];
            P[t][0] = xb[n * 3 + 0];
            P[t][1] = xb[n * 3 + 1];
            P[t][2] = xb[n * 3 + 2];
        }
        __syncthreads();

        // conv1: 3 -> 64
        {
            int ch = t & 63, p0 = t >> 6;
            float wa = __ldg(w1 + ch * 3 + 0), wb = __ldg(w1 + ch * 3 + 1),
                  wc = __ldg(w1 + ch * 3 + 2), bb = __ldg(b1 + ch);
#pragma unroll
            for (int k = 0; k < 4; k++) {
                int p = p0 + 8 * k;
                float v = fmaf(wa, P[p][0], fmaf(wb, P[p][1], fmaf(wc, P[p][2], bb)));
                Ha[p][ch] = fmaxf(v, 0.0f);
            }
        }
        __syncthreads();

        // conv2: 64 -> 64 (Ha -> Hb)
        {
            int ch = t & 63, p0 = t >> 6;
            float bb = __ldg(b2 + ch);
            float a0 = bb, a1 = bb, a2 = bb, a3 = bb;
            const float* wr = w2 + ch * 64;
#pragma unroll 8
            for (int j = 0; j < 64; j++) {
                float ww = __ldg(wr + j);
                a0 = fmaf(ww, Ha[p0 +  0][j], a0);
                a1 = fmaf(ww, Ha[p0 +  8][j], a1);
                a2 = fmaf(ww, Ha[p0 + 16][j], a2);
                a3 = fmaf(ww, Ha[p0 + 24][j], a3);
            }
            Hb[p0 +  0][ch] = fmaxf(a0, 0.0f);
            Hb[p0 +  8][ch] = fmaxf(a1, 0.0f);
            Hb[p0 + 16][ch] = fmaxf(a2, 0.0f);
            Hb[p0 + 24][ch] = fmaxf(a3, 0.0f);
        }
        __syncthreads();

        // conv3: 64 -> 64 (Hb -> Ha)
        {
            int ch = t & 63, p0 = t >> 6;
            float bb = __ldg(b3 + ch);
            float a0 = bb, a1 = bb, a2 = bb, a3 = bb;
            const float* wr = w3 + ch * 64;
#pragma unroll 8
            for (int j = 0; j < 64; j++) {
                float ww = __ldg(wr + j);
                a0 = fmaf(ww, Hb[p0 +  0][j], a0);
                a1 = fmaf(ww, Hb[p0 +  8][j], a1);
                a2 = fmaf(ww, Hb[p0 + 16][j], a2);
                a3 = fmaf(ww, Hb[p0 + 24][j], a3);
            }
            Ha[p0 +  0][ch] = fmaxf(a0, 0.0f);
            Ha[p0 +  8][ch] = fmaxf(a1, 0.0f);
            Ha[p0 + 16][ch] = fmaxf(a2, 0.0f);
            Ha[p0 + 24][ch] = fmaxf(a3, 0.0f);
        }
        __syncthreads();

        // conv4: 64 -> 128 (Ha -> g_h4, coalesced)
        {
            int oc = t & 127, p0 = t >> 7;
            float bb = __ldg(b4 + oc);
            float acc[8];
#pragma unroll
            for (int k = 0; k < 8; k++) acc[k] = bb;
            const float* wr = w4 + oc * 64;
#pragma unroll 4
            for (int j = 0; j < 64; j++) {
                float ww = __ldg(wr + j);
#pragma unroll
                for (int k = 0; k < 8; k++)
                    acc[k] = fmaf(ww, Ha[p0 + 4 * k][j], acc[k]);
            }
            float* out = g_h4 + (size_t)(b * NC + ci) * KNN * 128;
#pragma unroll
            for (int k = 0; k < 8; k++)
                out[(p0 + 4 * k) * 128 + oc] = fmaxf(acc[k], 0.0f);
        }
        __syncthreads();
    }
}

// ===========================================================================
// K3: conv5 (128->1024) + relu + position-max -> atomicMax into g_pool.
// Re-tiled: grid (ci-stride, NB, 16 oc-tiles of 64). Block 512 = 64 oc x
// 8 position-groups (4 positions each): only 512 serial FMAs per thread.
// ===========================================================================
__global__ __launch_bounds__(512) void k_conv5(const float* __restrict__ w5,
                                               const float* __restrict__ b5) {
    const int b = blockIdx.y, z = blockIdx.z;
    const int cnt = g_cnt[b];
    const int t = threadIdx.x;
    const int ocl = t & 63, pg = t >> 6;          // oc-local, position-group

    __shared__ float H[32 * 128];
    __shared__ float S[8][64];

    for (int ci = blockIdx.x; ci < cnt; ci += CONV5_GRID_X) {
        const float4* h4 = (const float4*)(g_h4 + (size_t)(b * NC + ci) * KNN * 128);
        float4* Hv = (float4*)H;
        for (int i = t; i < 1024; i += 512) Hv[i] = h4[i];
        __syncthreads();

        const int oc = z * 64 + ocl;
        const float* wr = w5 + (size_t)oc * 128;
        const int p0 = pg * 4;
        float a0 = 0.f, a1 = 0.f, a2 = 0.f, a3 = 0.f;
#pragma unroll 8
        for (int j = 0; j < 128; j++) {
            float ww = __ldg(wr + j);
            a0 = fmaf(ww, H[(p0 + 0) * 128 + j], a0);
            a1 = fmaf(ww, H[(p0 + 1) * 128 + j], a1);
            a2 = fmaf(ww, H[(p0 + 2) * 128 + j], a2);
            a3 = fmaf(ww, H[(p0 + 3) * 128 + j], a3);
        }
        float m = fmaxf(fmaxf(a0, a1), fmaxf(a2, a3));
        S[pg][ocl] = m;
        __syncthreads();
        if (t < 64) {
            float mm = S[0][t];
#pragma unroll
            for (int g = 1; g < 8; g++) mm = fmaxf(mm, S[g][t]);
            mm = fmaxf(mm + __ldg(b5 + z * 64 + t), 0.0f);
            atomicMax(&g_pool[b * 1024 + z * 64 + t], __float_as_int(mm));
        }
        __syncthreads();
    }
}

// ===========================================================================
// K4a: fc1 (1024 -> 512). One block per (o, b): 2048 blocks, 256 threads.
// ===========================================================================
__global__ __launch_bounds__(256) void k_fc1(const float* __restrict__ fw1,
                                             const float* __restrict__ fb1) {
    const int o = blockIdx.x, b = blockIdx.y, t = threadIdx.x;
    __shared__ float red[8];

    float4 w = __ldg((const float4*)(fw1 + (size_t)o * 1024) + t);
    float g0 = __int_as_float(g_pool[b * 1024 + 4 * t + 0]);
    float g1 = __int_as_float(g_pool[b * 1024 + 4 * t + 1]);
    float g2 = __int_as_float(g_pool[b * 1024 + 4 * t + 2]);
    float g3 = __int_as_float(g_pool[b * 1024 + 4 * t + 3]);
    float s = fmaf(w.x, g0, fmaf(w.y, g1, fmaf(w.z, g2, w.w * g3)));
#pragma unroll
    for (int off = 16; off > 0; off >>= 1)
        s += __shfl_down_sync(0xffffffffu, s, off);
    if ((t & 31) == 0) red[t >> 5] = s;
    __syncthreads();
    if (t == 0) {
        float acc = red[0];
#pragma unroll
        for (int j = 1; j < 8; j++) acc += red[j];
        g_a1[b * 512 + o] = fmaxf(acc + __ldg(fb1 + o), 0.0f);
    }
}

// ===========================================================================
// K4b: fc2 (512 -> 256). One block per (o, b): 1024 blocks, 128 threads.
// ===========================================================================
__global__ __launch_bounds__(128) void k_fc2(const float* __restrict__ fw2,
                                             const float* __restrict__ fb2) {
    const int o = blockIdx.x, b = blockIdx.y, t = threadIdx.x;
    __shared__ float red[4];

    float4 w = __ldg((const float4*)(fw2 + (size_t)o * 512) + t);
    const float* a1 = g_a1 + b * 512 + 4 * t;
    float s = fmaf(w.x, a1[0], fmaf(w.y, a1[1], fmaf(w.z, a1[2], w.w * a1[3])));
#pragma unroll
    for (int off = 16; off > 0; off >>= 1)
        s += __shfl_down_sync(0xffffffffu, s, off);
    if ((t & 31) == 0) red[t >> 5] = s;
    __syncthreads();
    if (t == 0) {
        float acc = ((red[0] + red[1]) + (red[2] + red[3]));
        g_a2[b * 256 + o] = fmaxf(acc + __ldg(fb2 + o), 0.0f);
    }
}

// ===========================================================================
// K4c: fc3 (256 -> 3). One block per batch; warp per output.
// ===========================================================================
__global__ __launch_bounds__(128) void k_fc3(const float* __restrict__ fw3,
                                             const float* __restrict__ fb3,
                                             float* __restrict__ out) {
    const int b = blockIdx.x, t = threadIdx.x;
    const int o = t >> 5, lane = t & 31;
    if (o >= 3) return;
    const float4* wr = (const float4*)(fw3 + (size_t)o * 256);
    const float* a2 = g_a2 + b * 256;
    float4 wA = __ldg(wr + lane);
    float4 wB = __ldg(wr + 32 + lane);
    float s = fmaf(wA.x, a2[4 * lane + 0], fmaf(wA.y, a2[4 * lane + 1],
              fmaf(wA.z, a2[4 * lane + 2], wA.w * a2[4 * lane + 3])));
    s = fmaf(wB.x, a2[128 + 4 * lane + 0], fmaf(wB.y, a2[128 + 4 * lane + 1],
        fmaf(wB.z, a2[128 + 4 * lane + 2], fmaf(wB.w, a2[128 + 4 * lane + 3], s))));
#pragma unroll
    for (int off = 16; off > 0; off >>= 1)
        s += __shfl_down_sync(0xffffffffu, s, off);
    if (lane == 0) out[b * 3 + o] = s + __ldg(fb3 + o);
}

// ===========================================================================
extern "C" void kernel_launch(void* const* d_in, const int* in_sizes, int n_in,
                              void* d_out, int out_size) {
    const float* x    = (const float*)d_in[0];
    const int*   far0 = (const int*)d_in[1];
    const float* w1 = (const float*)d_in[2];  const float* b1 = (const float*)d_in[3];
    const float* w2 = (const float*)d_in[4];  const float* b2 = (const float*)d_in[5];
    const float* w3 = (const float*)d_in[6];  const float* b3 = (const float*)d_in[7];
    const float* w4 = (const float*)d_in[8];  const float* b4 = (const float*)d_in[9];
    const float* w5 = (const float*)d_in[10]; const float* b5 = (const float*)d_in[11];
    const float* fw1 = (const float*)d_in[12]; const float* fb1 = (const float*)d_in[13];
    const float* fw2 = (const float*)d_in[14]; const float* fb2 = (const float*)d_in[15];
    const float* fw3 = (const float*)d_in[16]; const float* fb3 = (const float*)d_in[17];
    float* out = (float*)d_out;

    k_fps<<<NB + WARM_BLOCKS, 512>>>(x, far0, fw1, fw2, w5);
    k_fused<<<dim3(FUSED_GRID_X, NB), 512>>>(x, w1, b1, w2, b2, w3, b3, w4, b4);
    k_conv5<<<dim3(CONV5_GRID_X, NB, 16), 512>>>(w5, b5);
    k_fc1<<<dim3(512, NB), 256>>>(fw1, fb1);
    k_fc2<<<dim3(256, NB), 128>>>(fw2, fb2);
    k_fc3<<<NB, 128>>>(fw3, fb3, out);
}

// round 8
// speedup vs baseline: 1.5908x; 1.5742x over previous
#include <cuda_runtime.h>
#include <cuda_bf16.h>
#include <cstdint>

// ---------------------------------------------------------------------------
// cls_model, persistent single-kernel version.
// B=4, N=16384, C=3, N_C=1024, K=32
// Phases separated by software grid barriers (128 co-resident blocks):
//  P0 FPS(+cycle collapse) | pool zero | weight warm
//  P1 KNN(32) + conv1..4 -> g_h4
//  P2 conv5 (smem-staged weight tiles) + maxpool (atomicMax)
//  P3 fc1, P4 fc2, P5 fc3 -> out
// ---------------------------------------------------------------------------

#define NB 4
#define NPTS 16384
#define NC 1024
#define KNN 32
#define G 128          // persistent blocks; <=148 SMs, 1 block/SM => co-resident

// ---- device scratch (no allocations allowed) ----
__device__ int      g_cnt[NB];
__device__ float    g_cent[NB * NC * 3];
__device__ float    g_h4[(size_t)NB * NC * KNN * 128];
__device__ int      g_pool[NB * 1024];
__device__ float    g_a1[NB * 512];
__device__ float    g_a2[NB * 256];
__device__ float    g_sink[G];
__device__ unsigned g_bar_arrive = 0;
__device__ unsigned g_bar_gen = 0;

static __device__ __forceinline__ float f_inf() { return __int_as_float(0x7f800000); }
static __device__ __forceinline__ unsigned f_ord(float f) {
    unsigned b = __float_as_uint(f);
    return b ^ ((unsigned)(((int)b) >> 31) | 0x80000000u);
}

// Software grid barrier. Snapshot gen BEFORE arriving (race-free release).
// All G blocks resident (1 block/SM guaranteed by reg/thread budget) -> no deadlock.
static __device__ __forceinline__ void grid_bar() {
    __syncthreads();
    if (threadIdx.x == 0) {
        unsigned gen = ((volatile unsigned*)&g_bar_gen)[0];
        __threadfence();
        unsigned a = atomicAdd(&g_bar_arrive, 1u);
        if (a == (unsigned)G - 1u) {
            g_bar_arrive = 0u;
            __threadfence();
            atomicAdd(&g_bar_gen, 1u);
        } else {
            while (((volatile unsigned*)&g_bar_gen)[0] == gen) __nanosleep(64);
        }
        __threadfence();
    }
    __syncthreads();
}

// SMEM pool, manually phase-aliased:
//  P0 (fps): seen[512] u32 @0
//  P1: cand u64[512] @0 | Ha[32][65] @4096 | Hb[32][65] @12416 | P[32][4] @20736
//  P2: H4[32*128] @0 (16384) | W[32*129] @16384 (16512) | S[16*32] @32896 (2048)
#define SH_BYTES 35840
__shared__ __align__(16) char SH[SH_BYTES];

__global__ __launch_bounds__(512) void k_all(
    const float* __restrict__ x,    const int* __restrict__ far0,
    const float* __restrict__ w1,  const float* __restrict__ b1,
    const float* __restrict__ w2,  const float* __restrict__ b2,
    const float* __restrict__ w3,  const float* __restrict__ b3,
    const float* __restrict__ w4,  const float* __restrict__ b4,
    const float* __restrict__ w5,  const float* __restrict__ b5,
    const float* __restrict__ fw1, const float* __restrict__ fb1,
    const float* __restrict__ fw2, const float* __restrict__ fb2,
    const float* __restrict__ fw3, const float* __restrict__ fb3,
    float* __restrict__ out) {
    const int bid = blockIdx.x;
    const int t = threadIdx.x;
    const int lane = t & 31, wrp = t >> 5;

    __shared__ float cc[3];
    __shared__ float rd[16]; __shared__ int rn[16];
    __shared__ float rx[16], ry[16], rz[16];
    __shared__ int sdone;
    __shared__ int wlist[KNN];

    // ============================ P0 ======================================
    if (bid < NB) {
        // ---------------- FPS (bit-exact vs reference) --------------------
        const int b = bid;
        const float* xb = x + (size_t)b * NPTS * 3;
        unsigned* seen = (unsigned*)SH;

        float px[32], py[32], pz[32];
#pragma unroll
        for (int i = 0; i < 32; i++) {
            int n = i * 512 + t;
            px[i] = xb[n * 3 + 0];
            py[i] = xb[n * 3 + 1];
            pz[i] = xb[n * 3 + 2];
        }
        seen[t] = 0u;
        __syncthreads();

        if (t == 0) {
            int f = far0[b];
            seen[f >> 5] = 1u << (f & 31);
            float cx = xb[f * 3 + 0], cy = xb[f * 3 + 1], cz = xb[f * 3 + 2];
            cc[0] = cx; cc[1] = cy; cc[2] = cz;
            g_cent[(b * NC + 0) * 3 + 0] = cx;
            g_cent[(b * NC + 0) * 3 + 1] = cy;
            g_cent[(b * NC + 0) * 3 + 2] = cz;
            sdone = 0;
        }
        __syncthreads();

        int cnt = 1;
        for (int it = 1; it < NC; it++) {
            float cx = cc[0], cy = cc[1], cz = cc[2];
            float best = -1.0f; int bn = 0;
            float bx = 0.f, by = 0.f, bz = 0.f;
#pragma unroll
            for (int i = 0; i < 32; i++) {
                float dx = __fsub_rn(px[i], cx);
                float dy = __fsub_rn(py[i], cy);
                float dz = __fsub_rn(pz[i], cz);
                float d = __fadd_rn(__fadd_rn(__fmul_rn(dx, dx), __fmul_rn(dy, dy)),
                                    __fmul_rn(dz, dz));
                int n = i * 512 + t;
                if (d > best) { best = d; bn = n; bx = px[i]; by = py[i]; bz = pz[i]; }
            }
#pragma unroll
            for (int o = 16; o > 0; o >>= 1) {
                float od = __shfl_down_sync(0xffffffffu, best, o);
                int   on = __shfl_down_sync(0xffffffffu, bn,   o);
                float ox = __shfl_down_sync(0xffffffffu, bx,   o);
                float oy = __shfl_down_sync(0xffffffffu, by,   o);
                float oz = __shfl_down_sync(0xffffffffu, bz,   o);
                if (od > best || (od == best && on < bn)) {
                    best = od; bn = on; bx = ox; by = oy; bz = oz;
                }
            }
            if (lane == 0) { rd[wrp] = best; rn[wrp] = bn; rx[wrp] = bx; ry[wrp] = by; rz[wrp] = bz; }
            __syncthreads();
            if (t == 0) {
                best = rd[0]; bn = rn[0]; bx = rx[0]; by = ry[0]; bz = rz[0];
                for (int j = 1; j < 16; j++) {
                    if (rd[j] > best || (rd[j] == best && rn[j] < bn)) {
                        best = rd[j]; bn = rn[j]; bx = rx[j]; by = ry[j]; bz = rz[j];
                    }
                }
                unsigned bit = 1u << (bn & 31);
                if (seen[bn >> 5] & bit) {
                    sdone = 1;          // cycle: all future centroids are repeats
                } else {
                    seen[bn >> 5] |= bit;
                    g_cent[(b * NC + cnt) * 3 + 0] = bx;
                    g_cent[(b * NC + cnt) * 3 + 1] = by;
                    g_cent[(b * NC + cnt) * 3 + 2] = bz;
                    cc[0] = bx; cc[1] = by; cc[2] = bz;
                }
            }
            __syncthreads();
            if (sdone) break;
            cnt++;
        }
        if (t == 0) g_cnt[b] = cnt;
    } else if (bid < 2 * NB) {
        // ---------------- zero maxpool accumulator ------------------------
        const int b = bid - NB;
        g_pool[b * 1024 + t] = 0;
        g_pool[b * 1024 + 512 + t] = 0;
    } else if (bid < 8 + 64) {
        // ---------------- warm L2 with FC / conv5 weights -----------------
        const int wb = bid - 8;
        float s = 0.0f;
        const float4* p1 = (const float4*)fw1;
        for (int i = wb * 512 + t; i < 512 * 256; i += 64 * 512) {
            float4 v = __ldg(p1 + i); s += v.x + v.y + v.z + v.w;
        }
        const float4* p2 = (const float4*)fw2;
        for (int i = wb * 512 + t; i < 256 * 128; i += 64 * 512) {
            float4 v = __ldg(p2 + i); s += v.x + v.y + v.z + v.w;
        }
        const float4* p5 = (const float4*)w5;
        for (int i = wb * 512 + t; i < 1024 * 32; i += 64 * 512) {
            float4 v = __ldg(p5 + i); s += v.x + v.y + v.z + v.w;
        }
        if (t == 0) g_sink[bid] = s;   // keep loads alive (output unused)
    }
    grid_bar();

    // Work-list prefix (every block, registers only)
    const int c0 = g_cnt[0], c1 = g_cnt[1], c2 = g_cnt[2], c3 = g_cnt[3];
    const int o1 = c0, o2 = c0 + c1, o3 = o2 + c2;
    const int T = o3 + c3;

    // ============================ P1: KNN + conv1..4 ======================
    {
        unsigned long long* cand = (unsigned long long*)SH;
        float (*Ha)[65] = (float (*)[65])(SH + 4096);
        float (*Hb)[65] = (float (*)[65])(SH + 12416);
        float (*P)[4]   = (float (*)[4])(SH + 20736);

        for (int u = bid; u < T; u += G) {
            int b, base;
            if (u < o1)      { b = 0; base = 0;  }
            else if (u < o2) { b = 1; base = o1; }
            else if (u < o3) { b = 2; base = o2; }
            else             { b = 3; base = o3; }
            const int ci = u - base;
            const float* xb = x + (size_t)b * NPTS * 3;

            // distances (bit-exact: (c2+x2) - 2*dot, each op rounded)
            const float cx = g_cent[(b * NC + ci) * 3 + 0];
            const float cy = g_cent[(b * NC + ci) * 3 + 1];
            const float cz = g_cent[(b * NC + ci) * 3 + 2];
            const float c2s = __fadd_rn(__fadd_rn(__fmul_rn(cx, cx), __fmul_rn(cy, cy)),
                                        __fmul_rn(cz, cz));
            float d[32];
#pragma unroll
            for (int i = 0; i < 32; i++) {
                int n = i * 512 + t;
                float X = xb[n * 3 + 0], Y = xb[n * 3 + 1], Z = xb[n * 3 + 2];
                float x2 = __fadd_rn(__fadd_rn(__fmul_rn(X, X), __fmul_rn(Y, Y)),
                                     __fmul_rn(Z, Z));
                float dt = __fadd_rn(__fadd_rn(__fmul_rn(cx, X), __fmul_rn(cy, Y)),
                                     __fmul_rn(cz, Z));
                d[i] = __fsub_rn(__fadd_rn(c2s, x2), __fmul_rn(2.0f, dt));
            }

            // warp-local top-32 extraction (shuffle-only; set == reference top_k)
            unsigned lu = 0xFFFFFFFFu; int ln = 1 << 30;
#pragma unroll
            for (int i = 0; i < 32; i++) {
                unsigned uu = f_ord(d[i]);
                int n = (i << 9) + t;
                if (uu < lu || (uu == lu && n < ln)) { lu = uu; ln = n; }
            }
            for (int r = 0; r < KNN; r++) {
                unsigned ru = lu; int rn2 = ln;
#pragma unroll
                for (int o = 16; o > 0; o >>= 1) {
                    unsigned ou = __shfl_down_sync(0xffffffffu, ru, o);
                    int      on = __shfl_down_sync(0xffffffffu, rn2, o);
                    if (ou < ru || (ou == ru && on < rn2)) { ru = ou; rn2 = on; }
                }
                ru  = __shfl_sync(0xffffffffu, ru, 0);
                rn2 = __shfl_sync(0xffffffffu, rn2, 0);
                if (lane == 0)
                    cand[wrp * 32 + r] = ((unsigned long long)ru << 14) | (unsigned)rn2;
                if (ln == rn2) {
#pragma unroll
                    for (int i = 0; i < 32; i++)
                        if ((i << 9) + t == rn2) d[i] = f_inf();
                    lu = 0xFFFFFFFFu; ln = 1 << 30;
#pragma unroll
                    for (int i = 0; i < 32; i++) {
                        unsigned uu = f_ord(d[i]);
                        int n = (i << 9) + t;
                        if (uu < lu || (uu == lu && n < ln)) { lu = uu; ln = n; }
                    }
                }
            }
            __syncthreads();

            // rank 512 candidates, keep 32 smallest (keys unique)
            {
                unsigned long long k0 = cand[t];
                int r = 0;
#pragma unroll 8
                for (int j = 0; j < 512; j++) r += (cand[j] < k0);
                if (r < KNN) wlist[r] = (int)(k0 & 0x3FFFull);
            }
            __syncthreads();

            if (t < KNN) {
                int n = wlist[t];
                P[t][0] = xb[n * 3 + 0];
                P[t][1] = xb[n * 3 + 1];
                P[t][2] = xb[n * 3 + 2];
            }
            __syncthreads();

            // conv1: 3 -> 64
            {
                int ch = t & 63, p0 = t >> 6;
                float wa = __ldg(w1 + ch * 3 + 0), wb = __ldg(w1 + ch * 3 + 1),
                      wc = __ldg(w1 + ch * 3 + 2), bb = __ldg(b1 + ch);
#pragma unroll
                for (int k = 0; k < 4; k++) {
                    int p = p0 + 8 * k;
                    float v = fmaf(wa, P[p][0], fmaf(wb, P[p][1], fmaf(wc, P[p][2], bb)));
                    Ha[p][ch] = fmaxf(v, 0.0f);
                }
            }
            __syncthreads();

            // conv2: 64 -> 64 (Ha -> Hb)
            {
                int ch = t & 63, p0 = t >> 6;
                float bb = __ldg(b2 + ch);
                float a0 = bb, a1 = bb, a2 = bb, a3 = bb;
                const float* wr = w2 + ch * 64;
#pragma unroll 8
                for (int j = 0; j < 64; j++) {
                    float ww = __ldg(wr + j);
                    a0 = fmaf(ww, Ha[p0 +  0][j], a0);
                    a1 = fmaf(ww, Ha[p0 +  8][j], a1);
                    a2 = fmaf(ww, Ha[p0 + 16][j], a2);
                    a3 = fmaf(ww, Ha[p0 + 24][j], a3);
                }
                Hb[p0 +  0][ch] = fmaxf(a0, 0.0f);
                Hb[p0 +  8][ch] = fmaxf(a1, 0.0f);
                Hb[p0 + 16][ch] = fmaxf(a2, 0.0f);
                Hb[p0 + 24][ch] = fmaxf(a3, 0.0f);
            }
            __syncthreads();

            // conv3: 64 -> 64 (Hb -> Ha)
            {
                int ch = t & 63, p0 = t >> 6;
                float bb = __ldg(b3 + ch);
                float a0 = bb, a1 = bb, a2 = bb, a3 = bb;
                const float* wr = w3 + ch * 64;
#pragma unroll 8
                for (int j = 0; j < 64; j++) {
                    float ww = __ldg(wr + j);
                    a0 = fmaf(ww, Hb[p0 +  0][j], a0);
                    a1 = fmaf(ww, Hb[p0 +  8][j], a1);
                    a2 = fmaf(ww, Hb[p0 + 16][j], a2);
                    a3 = fmaf(ww, Hb[p0 + 24][j], a3);
                }
                Ha[p0 +  0][ch] = fmaxf(a0, 0.0f);
                Ha[p0 +  8][ch] = fmaxf(a1, 0.0f);
                Ha[p0 + 16][ch] = fmaxf(a2, 0.0f);
                Ha[p0 + 24][ch] = fmaxf(a3, 0.0f);
            }
            __syncthreads();

            // conv4: 64 -> 128 (Ha -> g_h4, coalesced)
            {
                int oc = t & 127, p0 = t >> 7;
                float bb = __ldg(b4 + oc);
                float acc[8];
#pragma unroll
                for (int k = 0; k < 8; k++) acc[k] = bb;
                const float* wr = w4 + oc * 64;
#pragma unroll 4
                for (int j = 0; j < 64; j++) {
                    float ww = __ldg(wr + j);
#pragma unroll
                    for (int k = 0; k < 8; k++)
                        acc[k] = fmaf(ww, Ha[p0 + 4 * k][j], acc[k]);
                }
                float* oo = g_h4 + (size_t)(b * NC + ci) * KNN * 128;
#pragma unroll
                for (int k = 0; k < 8; k++)
                    oo[(p0 + 4 * k) * 128 + oc] = fmaxf(acc[k], 0.0f);
            }
            __syncthreads();   // smem reuse on next unit
        }
    }
    grid_bar();

    // ============================ P2: conv5 + maxpool =====================
    {
        float* H4 = (float*)SH;                 // 32*128
        float* W  = (float*)(SH + 16384);       // 32*129 (bank-padded)
        float* S  = (float*)(SH + 32896);       // 16*32

        const int nwork = T * 32;               // 32 oc-tiles of 32 channels
        for (int u = bid; u < nwork; u += G) {
            const int v = u >> 5, z = u & 31;
            int b, base;
            if (v < o1)      { b = 0; base = 0;  }
            else if (v < o2) { b = 1; base = o1; }
            else if (v < o3) { b = 2; base = o2; }
            else             { b = 3; base = o3; }
            const int ci = v - base;

            // stage h4 tile + w5 tile (coalesced)
            const float4* h4 = (const float4*)(g_h4 + (size_t)(b * NC + ci) * KNN * 128);
            float4* H4v = (float4*)H4;
            for (int i = t; i < 1024; i += 512) H4v[i] = h4[i];
            const float* wsrc = w5 + (size_t)(z * 32) * 128;
            for (int k = t; k < 4096; k += 512) {
                int r = k >> 7, j = k & 127;
                W[r * 129 + j] = __ldg(wsrc + k);
            }
            __syncthreads();

            // thread = (ocl 0..31, pg 0..15); 2 positions per thread
            const int ocl = t & 31, pg = t >> 5;
            const float* Wr = W + ocl * 129;
            const int p0 = pg * 2;
            float a0 = 0.f, a1 = 0.f;
#pragma unroll 8
            for (int j = 0; j < 128; j++) {
                float ww = Wr[j];
                a0 = fmaf(ww, H4[(p0 + 0) * 128 + j], a0);
                a1 = fmaf(ww, H4[(p0 + 1) * 128 + j], a1);
            }
            S[pg * 32 + ocl] = fmaxf(a0, a1);
            __syncthreads();
            if (t < 32) {
                float mm = S[t];
#pragma unroll
                for (int g = 1; g < 16; g++) mm = fmaxf(mm, S[g * 32 + t]);
                mm = fmaxf(mm + __ldg(b5 + z * 32 + t), 0.0f);  // relu(max+b)==max(relu(+b))
                atomicMax(&g_pool[b * 1024 + z * 32 + t], __float_as_int(mm));
            }
            __syncthreads();
        }
    }
    grid_bar();

    // ============================ P3: fc1 (warp per neuron) ===============
    {
        const int gw = bid * 16 + wrp;          // 0..2047 == (o<512, b<4)
        const int o = gw >> 2, b = gw & 3;
        const float4* wr = (const float4*)(fw1 + (size_t)o * 1024);
        float s = 0.0f;
#pragma unroll
        for (int k = 0; k < 8; k++) {
            int i = lane + 32 * k;
            float4 ww = __ldg(wr + i);
            float g0 = __int_as_float(g_pool[b * 1024 + 4 * i + 0]);
            float g1 = __int_as_float(g_pool[b * 1024 + 4 * i + 1]);
            float g2 = __int_as_float(g_pool[b * 1024 + 4 * i + 2]);
            float g3 = __int_as_float(g_pool[b * 1024 + 4 * i + 3]);
            s = fmaf(ww.x, g0, fmaf(ww.y, g1, fmaf(ww.z, g2, fmaf(ww.w, g3, s))));
        }
#pragma unroll
        for (int off = 16; off > 0; off >>= 1)
            s += __shfl_down_sync(0xffffffffu, s, off);
        if (lane == 0) g_a1[b * 512 + o] = fmaxf(s + __ldg(fb1 + o), 0.0f);
    }
    grid_bar();

    // ============================ P4: fc2 =================================
    {
        const int gw = bid * 16 + wrp;
        if (gw < 1024) {                        // (o<256, b<4)
            const int o = gw >> 2, b = gw & 3;
            const float4* wr = (const float4*)(fw2 + (size_t)o * 512);
            const float* a1p = g_a1 + b * 512;
            float s = 0.0f;
#pragma unroll
            for (int k = 0; k < 4; k++) {
                int i = lane + 32 * k;
                float4 ww = __ldg(wr + i);
                s = fmaf(ww.x, a1p[4 * i + 0], fmaf(ww.y, a1p[4 * i + 1],
                    fmaf(ww.z, a1p[4 * i + 2], fmaf(ww.w, a1p[4 * i + 3], s))));
            }
#pragma unroll
            for (int off = 16; off > 0; off >>= 1)
                s += __shfl_down_sync(0xffffffffu, s, off);
            if (lane == 0) g_a2[b * 256 + o] = fmaxf(s + __ldg(fb2 + o), 0.0f);
        }
    }
    grid_bar();

    // ============================ P5: fc3 -> out ==========================
    {
        const int gw = bid * 16 + wrp;
        if (gw < 12) {                          // (o<3, b<4)
            const int o = gw >> 2, b = gw & 3;
            const float4* wr = (const float4*)(fw3 + (size_t)o * 256);
            const float* a2p = g_a2 + b * 256;
            float s = 0.0f;
#pragma unroll
            for (int k = 0; k < 2; k++) {
                int i = lane + 32 * k;
                float4 ww = __ldg(wr + i);
                s = fmaf(ww.x, a2p[4 * i + 0], fmaf(ww.y, a2p[4 * i + 1],
                    fmaf(ww.z, a2p[4 * i + 2], fmaf(ww.w, a2p[4 * i + 3], s))));
            }
#pragma unroll
            for (int off = 16; off > 0; off >>= 1)
                s += __shfl_down_sync(0xffffffffu, s, off);
            if (lane == 0) out[b * 3 + o] = s + __ldg(fb3 + o);
        }
    }
}

// ===========================================================================
extern "C" void kernel_launch(void* const* d_in, const int* in_sizes, int n_in,
                              void* d_out, int out_size) {
    const float* x    = (const float*)d_in[0];
    const int*   far0 = (const int*)d_in[1];
    const float* w1 = (const float*)d_in[2];  const float* b1 = (const float*)d_in[3];
    const float* w2 = (const float*)d_in[4];  const float* b2 = (const float*)d_in[5];
    const float* w3 = (const float*)d_in[6];  const float* b3 = (const float*)d_in[7];
    const float* w4 = (const float*)d_in[8];  const float* b4 = (const float*)d_in[9];
    const float* w5 = (const float*)d_in[10]; const float* b5 = (const float*)d_in[11];
    const float* fw1 = (const float*)d_in[12]; const float* fb1 = (const float*)d_in[13];
    const float* fw2 = (const float*)d_in[14]; const float* fb2 = (const float*)d_in[15];
    const float* fw3 = (const float*)d_in[16]; const float* fb3 = (const float*)d_in[17];
    float* out = (float*)d_out;

    k_all<<<G, 512>>>(x, far0, w1, b1, w2, b2, w3, b3, w4, b4, w5, b5,
                      fw1, fb1, fw2, fb2, fw3, fb3, out);
}